// round 11
// baseline (speedup 1.0000x reference)
#include <cuda_runtime.h>
#include <cuda_bf16.h>

// RHS of 2-field Burgers-like PDE on nonuniform 2048x4096 grid.
// Inputs (metadata order): t[1], state[2*NX*NY], x[NX], y[NY], mu[1]
// Output: [2, NX, NY] float32.
//
// R11: R6 structure (RT=4, front-batched 6-row float4 window) + precomputed
// coefficients with d1 NEGATED and d2 PRE-SCALED BY MU, single-chain d2
// accumulation, 128-thread blocks targeting 5 blocks/SM.

#define NX_MAX 2048
#define NY_MAX 4096
#define FULLMASK 0xffffffffu

// x-direction coefficients: AoS (warp-uniform broadcast loads)
__device__ float4 g_cxA[NX_MAX];   // (-d1a, -d1b, -d1c, mu*d2a)
__device__ float2 g_cxB[NX_MAX];   // (mu*d2b, mu*d2c)
// y-direction coefficients: SoA, 16B-aligned for float4 loads
__device__ __align__(16) float g_cy1a[NY_MAX];   // -d1a
__device__ __align__(16) float g_cy1b[NY_MAX];   // -d1b
__device__ __align__(16) float g_cy1c[NY_MAX];   // -d1c
__device__ __align__(16) float g_cy2a[NY_MAX];   // mu*d2a
__device__ __align__(16) float g_cy2b[NY_MAX];   // mu*d2b
__device__ __align__(16) float g_cy2c[NY_MAX];   // mu*d2c

__device__ __forceinline__ void stencil_coeffs(const float* __restrict__ g,
                                               int n, int k, float mu, float* c) {
    if (k == 0) {
        float hA = g[1] - g[0], hB = g[2] - g[1];
        c[0] = -(2.f * hA + hB) / (hA * (hA + hB));
        c[1] = (hA + hB) / (hA * hB);
        c[2] = -hA / (hB * (hA + hB));
        c[3] = 2.f / (hA * (hA + hB));
        c[4] = -2.f / (hA * hB);
        c[5] = 2.f / (hB * (hA + hB));
    } else if (k == n - 1) {
        float hC = g[n - 2] - g[n - 3], hD = g[n - 1] - g[n - 2];
        c[0] = hD / (hC * (hC + hD));
        c[1] = -(hC + hD) / (hC * hD);
        c[2] = (hC + 2.f * hD) / (hD * (hC + hD));
        c[3] = 2.f / (hC * (hC + hD));
        c[4] = -2.f / (hC * hD);
        c[5] = 2.f / (hD * (hC + hD));
    } else {
        float h1 = g[k] - g[k - 1], h2 = g[k + 1] - g[k];
        c[0] = -h2 / (h1 * (h1 + h2));
        c[1] = (h2 - h1) / (h1 * h2);
        c[2] = h1 / (h2 * (h1 + h2));
        c[3] = 2.f / (h1 * (h1 + h2));
        c[4] = -2.f / (h1 * h2);
        c[5] = 2.f / (h2 * (h1 + h2));
    }
    c[0] = -c[0]; c[1] = -c[1]; c[2] = -c[2];   // negate d1 -> advection is FMA
    c[3] *= mu; c[4] *= mu; c[5] *= mu;         // fold mu into d2
}

__global__ __launch_bounds__(256)
void coeff_kernel(const float* __restrict__ x, int nx,
                  const float* __restrict__ y, int ny,
                  const float* __restrict__ mu_p) {
    int k = blockIdx.x * blockDim.x + threadIdx.x;
    float mu = mu_p[0];
    float c[6];
    if (k < nx) {
        stencil_coeffs(x, nx, k, mu, c);
        g_cxA[k] = make_float4(c[0], c[1], c[2], c[3]);
        g_cxB[k] = make_float2(c[4], c[5]);
    }
    if (k < ny) {
        stencil_coeffs(y, ny, k, mu, c);
        g_cy1a[k] = c[0]; g_cy1b[k] = c[1]; g_cy1c[k] = c[2];
        g_cy2a[k] = c[3]; g_cy2b[k] = c[4]; g_cy2c[k] = c[5];
    }
}

__device__ __forceinline__ float4 ld4(const float* p) {
    return *reinterpret_cast<const float4*>(p);
}
__device__ __forceinline__ void st4(float* p, float4 v) {
    *reinterpret_cast<float4*>(p) = v;
}

// Warp owns 128 aligned columns; lane owns 4 (float4). Each thread computes
// 4 consecutive i-rows from a front-batched 6-row window (rows i0-1..i0+4).
__global__ __launch_bounds__(128, 5)
void rhs_kernel(const float* __restrict__ state,
                float* __restrict__ out, int nx, int ny) {
    const int lane = threadIdx.x;
    const int base = blockIdx.x * 128;
    const int j0 = base + lane * 4;
    if (j0 >= ny) return;
    const int i0 = (blockIdx.y * blockDim.y + threadIdx.y) * 4;
    const unsigned plane = (unsigned)nx * (unsigned)ny;
    const float* __restrict__ u = state;
    const float* __restrict__ v = state + plane;

    // Front-batched 6-row window (rows i0-1 .. i0+4, i-clamped)
    float4 uc[6], vc[6];
#pragma unroll
    for (int k = 0; k < 6; k++) {
        int ir = min(max(i0 - 1 + k, 0), nx - 1);
        unsigned off = (unsigned)ir * (unsigned)ny + (unsigned)j0;
        uc[k] = ld4(u + off);
        vc[k] = ld4(v + off);
    }

    // Halo columns (warp-edge neighbors), front-batched.
    float hu[4] = {0, 0, 0, 0}, hv[4] = {0, 0, 0, 0};
    const bool is_halo = (lane == 0) || (lane == 31);
    if (is_halo) {
        int jh = (lane == 0) ? max(base - 1, 0) : min(base + 128, ny - 1);
#pragma unroll
        for (int r = 0; r < 4; r++) {
            unsigned off = (unsigned)(i0 + r) * (unsigned)ny + (unsigned)jh;
            hu[r] = __ldg(u + off);
            hv[r] = __ldg(v + off);
        }
    }

    // y-coefficients for this lane's 4 columns (d1 negated, d2 mu-scaled)
    const float4 c1a = ld4(&g_cy1a[j0]);
    const float4 c1b = ld4(&g_cy1b[j0]);
    const float4 c1c = ld4(&g_cy1c[j0]);
    const float4 c2a = ld4(&g_cy2a[j0]);
    const float4 c2b = ld4(&g_cy2b[j0]);
    const float4 c2c = ld4(&g_cy2c[j0]);

    const bool e0b = (j0 == 0);            // column .x is the global left edge
    const bool e3b = (j0 + 3 == ny - 1);   // column .w is the global right edge
    const unsigned obase = (unsigned)i0 * (unsigned)ny + (unsigned)j0;

#pragma unroll
    for (int r = 0; r < 4; r++) {
        const int i = i0 + r;
        const float4 U = uc[r + 1], V = vc[r + 1];

        // Warp-edge neighbors via shuffle; lanes 0/31 patch from halo loads.
        float lu = __shfl_up_sync(FULLMASK, U.w, 1);
        float ru = __shfl_down_sync(FULLMASK, U.x, 1);
        float lv = __shfl_up_sync(FULLMASK, V.w, 1);
        float rv = __shfl_down_sync(FULLMASK, V.x, 1);
        if (lane == 0)  { lu = hu[r]; lv = hv[r]; }
        if (lane == 31) { ru = hu[r]; rv = hv[r]; }

        // Per-element y-stencil triples. At j==0 the one-sided stencil reads
        // columns {0,1,2} = (.x,.y,.z); at j==ny-1 it reads (.y,.z,.w).
        float a0u = e0b ? U.x : lu,  b0u = e0b ? U.y : U.x, g0u = e0b ? U.z : U.y;
        float a0v = e0b ? V.x : lv,  b0v = e0b ? V.y : V.x, g0v = e0b ? V.z : V.y;
        float a3u = e3b ? U.y : U.z, b3u = e3b ? U.z : U.w, g3u = e3b ? U.w : ru;
        float a3v = e3b ? V.y : V.z, b3v = e3b ? V.z : V.w, g3v = e3b ? V.w : rv;

        // x-stencil triples from the window. Interior: rows r,r+1,r+2 about i.
        // i==0 row is fully zeroed by the reference (garbage OK); i==nx-1
        // (r==3) one-sided uses rows nx-3..nx-1 = uc[2..4].
        const bool lastr = (r == 3) && (i == nx - 1);
        const float4 X0 = lastr ? uc[2] : uc[r];
        const float4 X1 = lastr ? uc[3] : uc[r + 1];
        const float4 X2 = lastr ? uc[4] : uc[r + 2];
        const float4 Y0 = lastr ? vc[2] : vc[r];
        const float4 Y1 = lastr ? vc[3] : vc[r + 1];
        const float4 Y2 = lastr ? vc[4] : vc[r + 2];

        const float4 cxa = g_cxA[i];   // warp-uniform (-d1, mu*d2a)
        const float2 cxb = g_cxB[i];   // (mu*d2b, mu*d2c)

        float4 du, dv;
        // Element 0 (uses a0/b0/g0 triple)
        {
            float nd1y = c1a.x * a0u + c1b.x * b0u + c1c.x * g0u;
            float nd1yv = c1a.x * a0v + c1b.x * b0v + c1c.x * g0v;
            float nd1x = cxa.x * X0.x + cxa.y * X1.x + cxa.z * X2.x;
            float nd1xv = cxa.x * Y0.x + cxa.y * Y1.x + cxa.z * Y2.x;
            float su = fmaf(c2a.x, a0u, 0.01f);
            su = fmaf(c2b.x, b0u, su); su = fmaf(c2c.x, g0u, su);
            su = fmaf(cxa.w, X0.x, su); su = fmaf(cxb.x, X1.x, su); su = fmaf(cxb.y, X2.x, su);
            du.x = fmaf(U.x, nd1x, fmaf(V.x, nd1y, su));
            float sv = c2a.x * a0v;
            sv = fmaf(c2b.x, b0v, sv); sv = fmaf(c2c.x, g0v, sv);
            sv = fmaf(cxa.w, Y0.x, sv); sv = fmaf(cxb.x, Y1.x, sv); sv = fmaf(cxb.y, Y2.x, sv);
            dv.x = fmaf(U.x, nd1xv, fmaf(V.x, nd1yv, sv));
        }
        // Element 1 (triple U.x,U.y,U.z)
        {
            float nd1y = c1a.y * U.x + c1b.y * U.y + c1c.y * U.z;
            float nd1yv = c1a.y * V.x + c1b.y * V.y + c1c.y * V.z;
            float nd1x = cxa.x * X0.y + cxa.y * X1.y + cxa.z * X2.y;
            float nd1xv = cxa.x * Y0.y + cxa.y * Y1.y + cxa.z * Y2.y;
            float su = fmaf(c2a.y, U.x, 0.01f);
            su = fmaf(c2b.y, U.y, su); su = fmaf(c2c.y, U.z, su);
            su = fmaf(cxa.w, X0.y, su); su = fmaf(cxb.x, X1.y, su); su = fmaf(cxb.y, X2.y, su);
            du.y = fmaf(U.y, nd1x, fmaf(V.y, nd1y, su));
            float sv = c2a.y * V.x;
            sv = fmaf(c2b.y, V.y, sv); sv = fmaf(c2c.y, V.z, sv);
            sv = fmaf(cxa.w, Y0.y, sv); sv = fmaf(cxb.x, Y1.y, sv); sv = fmaf(cxb.y, Y2.y, sv);
            dv.y = fmaf(U.y, nd1xv, fmaf(V.y, nd1yv, sv));
        }
        // Element 2 (triple U.y,U.z,U.w)
        {
            float nd1y = c1a.z * U.y + c1b.z * U.z + c1c.z * U.w;
            float nd1yv = c1a.z * V.y + c1b.z * V.z + c1c.z * V.w;
            float nd1x = cxa.x * X0.z + cxa.y * X1.z + cxa.z * X2.z;
            float nd1xv = cxa.x * Y0.z + cxa.y * Y1.z + cxa.z * Y2.z;
            float su = fmaf(c2a.z, U.y, 0.01f);
            su = fmaf(c2b.z, U.z, su); su = fmaf(c2c.z, U.w, su);
            su = fmaf(cxa.w, X0.z, su); su = fmaf(cxb.x, X1.z, su); su = fmaf(cxb.y, X2.z, su);
            du.z = fmaf(U.z, nd1x, fmaf(V.z, nd1y, su));
            float sv = c2a.z * V.y;
            sv = fmaf(c2b.z, V.z, sv); sv = fmaf(c2c.z, V.w, sv);
            sv = fmaf(cxa.w, Y0.z, sv); sv = fmaf(cxb.x, Y1.z, sv); sv = fmaf(cxb.y, Y2.z, sv);
            dv.z = fmaf(U.z, nd1xv, fmaf(V.z, nd1yv, sv));
        }
        // Element 3 (uses a3/b3/g3 triple)
        {
            float nd1y = c1a.w * a3u + c1b.w * b3u + c1c.w * g3u;
            float nd1yv = c1a.w * a3v + c1b.w * b3v + c1c.w * g3v;
            float nd1x = cxa.x * X0.w + cxa.y * X1.w + cxa.z * X2.w;
            float nd1xv = cxa.x * Y0.w + cxa.y * Y1.w + cxa.z * Y2.w;
            float su = fmaf(c2a.w, a3u, 0.01f);
            su = fmaf(c2b.w, b3u, su); su = fmaf(c2c.w, g3u, su);
            su = fmaf(cxa.w, X0.w, su); su = fmaf(cxb.x, X1.w, su); su = fmaf(cxb.y, X2.w, su);
            du.w = fmaf(U.w, nd1x, fmaf(V.w, nd1y, su));
            float sv = c2a.w * a3v;
            sv = fmaf(c2b.w, b3v, sv); sv = fmaf(c2c.w, g3v, sv);
            sv = fmaf(cxa.w, Y0.w, sv); sv = fmaf(cxb.x, Y1.w, sv); sv = fmaf(cxb.y, Y2.w, sv);
            dv.w = fmaf(U.w, nd1xv, fmaf(V.w, nd1yv, sv));
        }

        // Boundary zeroing per reference (entire i==0 row zeroed for both)
        if (i == 0) { du = make_float4(0.f, 0.f, 0.f, 0.f);
                      dv = make_float4(0.f, 0.f, 0.f, 0.f); }
        if (e0b) { du.x = 0.f; dv.x = 0.f; }
        if (e3b) { du.w = 0.f; }

        unsigned o = obase + (unsigned)r * (unsigned)ny;
        st4(out + o, du);
        st4(out + plane + o, dv);
    }
}

extern "C" void kernel_launch(void* const* d_in, const int* in_sizes, int n_in,
                              void* d_out, int out_size) {
    const float* state = (const float*)d_in[1];
    const float* x = (const float*)d_in[2];
    const float* y = (const float*)d_in[3];
    const float* mu = (const float*)d_in[4];
    int nx = in_sizes[2];
    int ny = in_sizes[3];
    float* out = (float*)d_out;

    int nmax = nx > ny ? nx : ny;
    coeff_kernel<<<(nmax + 255) / 256, 256>>>(x, nx, y, ny, mu);

    dim3 block(32, 4);                        // warp = 128 columns, 16 i-rows/block
    dim3 grid((ny + 127) / 128, (nx + 15) / 16);
    rhs_kernel<<<grid, block>>>(state, out, nx, ny);
}